// round 16
// baseline (speedup 1.0000x reference)
#include <cuda_runtime.h>
#include <cuda_fp16.h>
#include <math.h>
#include <stdint.h>

#define LQ 2048
#define HID 2048
#define NH 16
#define NKV 4
#define HD 128
#define INTER 8192
#define KVW (NKV*HD)   // 512

// ---------------- scratch (device globals; no allocation allowed) ----------------
__device__ __half g_normed[LQ*HID];
__device__ __half g_qh[LQ*HID];
__device__ __half g_kh[LQ*KVW];
__device__ __half g_vh[LQ*KVW];
__device__ __half g_attn[LQ*HID];
__device__ float  g_h1[LQ*HID];
__device__ __half g_n2[LQ*HID];
__device__ __half g_act[LQ*INTER];
// fp16 weight copies
__device__ __half w_q[HID*HID];
__device__ __half w_k[KVW*HID];
__device__ __half w_v[KVW*HID];
__device__ __half w_o[HID*HID];
__device__ __half w_g[INTER*HID];
__device__ __half w_u[INTER*HID];
__device__ __half w_d[HID*INTER];

// ---------------- PTX helpers ----------------
__device__ __forceinline__ void cp16(uint32_t dst, const void* src)
{
    asm volatile("cp.async.cg.shared.global [%0], [%1], 16;\n" :: "r"(dst), "l"(src));
}
__device__ __forceinline__ void cp_commit() { asm volatile("cp.async.commit_group;\n"); }
__device__ __forceinline__ void cp_wait1()  { asm volatile("cp.async.wait_group 1;\n"); }
__device__ __forceinline__ void cp_wait0()  { asm volatile("cp.async.wait_group 0;\n"); }

__device__ __forceinline__ void ldsm4(uint32_t addr, uint32_t& r0, uint32_t& r1,
                                      uint32_t& r2, uint32_t& r3)
{
    asm volatile("ldmatrix.sync.aligned.m8n8.x4.shared.b16 {%0,%1,%2,%3}, [%4];\n"
                 : "=r"(r0), "=r"(r1), "=r"(r2), "=r"(r3) : "r"(addr));
}
__device__ __forceinline__ void ldsm4t(uint32_t addr, uint32_t& r0, uint32_t& r1,
                                       uint32_t& r2, uint32_t& r3)
{
    asm volatile("ldmatrix.sync.aligned.m8n8.x4.trans.shared.b16 {%0,%1,%2,%3}, [%4];\n"
                 : "=r"(r0), "=r"(r1), "=r"(r2), "=r"(r3) : "r"(addr));
}
__device__ __forceinline__ void mma_f16(float* d, uint32_t a0, uint32_t a1,
                                        uint32_t a2, uint32_t a3,
                                        uint32_t b0, uint32_t b1)
{
    asm volatile("mma.sync.aligned.m16n8k16.row.col.f32.f16.f16.f32 "
                 "{%0,%1,%2,%3},{%4,%5,%6,%7},{%8,%9},{%0,%1,%2,%3};\n"
                 : "+f"(d[0]), "+f"(d[1]), "+f"(d[2]), "+f"(d[3])
                 : "r"(a0), "r"(a1), "r"(a2), "r"(a3), "r"(b0), "r"(b1));
}

// ---------------- weight conversion (split: qkv / ogud) ----------------
__device__ __forceinline__ void conv_seg(const float* s, __half* d, int n)
{
    int n8 = n >> 3;
    const float4* s4p = (const float4*)s;
    uint4* d4p = (uint4*)d;
    int stride = gridDim.x * blockDim.x;
    for (int i = blockIdx.x * blockDim.x + threadIdx.x; i < n8; i += stride) {
        float4 a = s4p[2 * i];
        float4 b = s4p[2 * i + 1];
        __half2 h0 = __floats2half2_rn(a.x, a.y);
        __half2 h1 = __floats2half2_rn(a.z, a.w);
        __half2 h2 = __floats2half2_rn(b.x, b.y);
        __half2 h3 = __floats2half2_rn(b.z, b.w);
        uint4 o;
        o.x = *(const uint32_t*)&h0; o.y = *(const uint32_t*)&h1;
        o.z = *(const uint32_t*)&h2; o.w = *(const uint32_t*)&h3;
        d4p[i] = o;
    }
}
__global__ void convert_qkv(const float* __restrict__ sq, const float* __restrict__ sk,
                            const float* __restrict__ sv,
                            __half* __restrict__ dq, __half* __restrict__ dk,
                            __half* __restrict__ dv)
{
    int seg = blockIdx.y;
    if (seg == 0) conv_seg(sq, dq, HID * HID);
    else if (seg == 1) conv_seg(sk, dk, KVW * HID);
    else conv_seg(sv, dv, KVW * HID);
}
__global__ void convert_ogud(const float* __restrict__ so, const float* __restrict__ sg,
                             const float* __restrict__ su, const float* __restrict__ sd,
                             __half* __restrict__ dmo, __half* __restrict__ dmg,
                             __half* __restrict__ dmu, __half* __restrict__ dmd)
{
    int seg = blockIdx.y;
    if (seg == 0) conv_seg(so, dmo, HID * HID);
    else if (seg == 1) conv_seg(sg, dmg, INTER * HID);
    else if (seg == 2) conv_seg(su, dmu, INTER * HID);
    else conv_seg(sd, dmd, HID * INTER);
}

// ---------------- RMSNorm (vectorized, fp16 output) ----------------
__global__ void rmsnorm_h(const float* __restrict__ x, const float* __restrict__ w,
                          __half* __restrict__ o)
{
    int row = blockIdx.x;
    int tid = threadIdx.x;           // 512 threads; 512*4 = 2048 = HID
    const float4* xr = (const float4*)(x + (size_t)row * HID);
    float4 v = xr[tid];
    float ss = v.x * v.x + v.y * v.y + v.z * v.z + v.w * v.w;
    #pragma unroll
    for (int off = 16; off; off >>= 1) ss += __shfl_xor_sync(0xffffffffu, ss, off);
    __shared__ float red[16];
    __shared__ float sscale;
    if ((tid & 31) == 0) red[tid >> 5] = ss;
    __syncthreads();
    if (tid == 0) {
        float t = 0.f;
        #pragma unroll
        for (int i = 0; i < 16; i++) t += red[i];
        sscale = rsqrtf(t / (float)HID + 1e-6f);
    }
    __syncthreads();
    float scale = sscale;
    float4 wv = ((const float4*)w)[tid];
    __half2 h0 = __floats2half2_rn(v.x * scale * wv.x, v.y * scale * wv.y);
    __half2 h1 = __floats2half2_rn(v.z * scale * wv.z, v.w * scale * wv.w);
    uint2 ov; ov.x = *(const uint32_t*)&h0; ov.y = *(const uint32_t*)&h1;
    ((uint2*)(o + (size_t)row * HID))[tid] = ov;
}

// ---------------- fp16 staging: 128 rows x 64 halves (128B/row) per matrix ----------------
__device__ __forceinline__ void stage_ab_h(uint32_t s, const __half* gA, const __half* gB,
                                           int K, int tid)
{
    #pragma unroll
    for (int i = 0; i < 4; i++) {
        int c = tid + i * 256;
        int row = c >> 3, g = c & 7;
        uint32_t off = (uint32_t)(row * 128 + ((g ^ (row & 7)) << 4));
        cp16(s + off,         gA + (size_t)row * K + g * 8);
        cp16(s + 16384 + off, gB + (size_t)row * K + g * 8);
    }
}
__device__ __forceinline__ void stage_agu_h(uint32_t s, const __half* gA, const __half* gG,
                                            const __half* gU, int K, int tid)
{
    #pragma unroll
    for (int i = 0; i < 4; i++) {
        int c = tid + i * 256;
        int row = c >> 3, g = c & 7;
        uint32_t off = (uint32_t)(row * 128 + ((g ^ (row & 7)) << 4));
        cp16(s + off, gA + (size_t)row * K + g * 8);
    }
    #pragma unroll
    for (int i = 0; i < 2; i++) {
        int c = tid + i * 256;
        int row = c >> 3, g = c & 7;
        uint32_t off = (uint32_t)(row * 128 + ((g ^ (row & 7)) << 4));
        cp16(s + 16384 + off, gG + (size_t)row * K + g * 8);
        cp16(s + 24576 + off, gU + (size_t)row * K + g * 8);
    }
}

// ---------------- fp16 GEMM core: 128x128 block, k-tile 64, 3-stage ----------------
// epi 0: C=acc(f32) ; 1: C=acc+aux(f32) ; 4: Ch=half(acc) ; 5: C=f32 AND Ch=half
__device__ __forceinline__ void gemm_core_h(
    const __half* __restrict__ gA, const __half* __restrict__ gB,
    float* __restrict__ C, __half* __restrict__ Ch,
    int K, int Nc, int crow0, int ccol0,
    const float* __restrict__ aux, int epi, uint32_t sbase)
{
    int tid = threadIdx.x, lane = tid & 31, warp = tid >> 5;
    int wm = (warp & 3) << 5;
    int wn = (warp >> 2) << 6;

    float acc[2][8][4];
    #pragma unroll
    for (int mi = 0; mi < 2; mi++)
        #pragma unroll
        for (int n = 0; n < 8; n++)
            #pragma unroll
            for (int j = 0; j < 4; j++) acc[mi][n][j] = 0.f;

    int a_r   = lane & 15;
    int a_kgo = lane >> 4;
    int b_r   = ((lane >> 4) << 3) + (lane & 7);
    int b_kgo = (lane >> 3) & 1;

    int kTiles = K >> 6;
    stage_ab_h(sbase,         gA,      gB,      K, tid); cp_commit();
    stage_ab_h(sbase + 32768, gA + 64, gB + 64, K, tid); cp_commit();
    cp_wait1();
    __syncthreads();

    int scur = 0, sfill = 2;   // rotating stage indices
    for (int kt = 0; kt < kTiles; kt++) {
        if (kt + 2 < kTiles) {
            stage_ab_h(sbase + sfill * 32768, gA + (kt + 2) * 64, gB + (kt + 2) * 64, K, tid);
        }
        cp_commit();
        uint32_t sA = sbase + scur * 32768;
        uint32_t sB = sA + 16384;
        #pragma unroll
        for (int kk = 0; kk < 4; kk++) {
            uint32_t afr[2][4], bfr[4][4];
            #pragma unroll
            for (int mi = 0; mi < 2; mi++) {
                int arow = wm + mi * 16 + a_r;
                int akg  = kk * 2 + a_kgo;
                uint32_t ad = sA + (uint32_t)(arow * 128 + ((akg ^ (arow & 7)) << 4));
                ldsm4(ad, afr[mi][0], afr[mi][1], afr[mi][2], afr[mi][3]);
            }
            #pragma unroll
            for (int nj = 0; nj < 4; nj++) {
                int brow = wn + nj * 16 + b_r;
                int bkg  = kk * 2 + b_kgo;
                uint32_t bd = sB + (uint32_t)(brow * 128 + ((bkg ^ (brow & 7)) << 4));
                ldsm4(bd, bfr[nj][0], bfr[nj][1], bfr[nj][2], bfr[nj][3]);
            }
            #pragma unroll
            for (int mi = 0; mi < 2; mi++)
                #pragma unroll
                for (int n = 0; n < 8; n++)
                    mma_f16(acc[mi][n],
                            afr[mi][0], afr[mi][1], afr[mi][2], afr[mi][3],
                            bfr[n >> 1][(n & 1) * 2], bfr[n >> 1][(n & 1) * 2 + 1]);
        }
        cp_wait1();
        __syncthreads();
        scur  = (scur  == 2) ? 0 : scur  + 1;
        sfill = (sfill == 2) ? 0 : sfill + 1;
    }

    int rb = crow0 + wm + (lane >> 2);
    int cb = ccol0 + wn + ((lane & 3) << 1);
    #pragma unroll
    for (int mi = 0; mi < 2; mi++) {
        #pragma unroll
        for (int n = 0; n < 8; n++) {
            int cc = cb + n * 8;
            #pragma unroll
            for (int h = 0; h < 2; h++) {
                int rr = rb + mi * 16 + h * 8;
                size_t idx = (size_t)rr * Nc + cc;
                float v0 = acc[mi][n][h * 2], v1 = acc[mi][n][h * 2 + 1];
                if (epi == 1) {
                    float2 x = *(const float2*)(aux + idx);
                    v0 += x.x; v1 += x.y;
                }
                if (epi != 4) {
                    float2 o; o.x = v0; o.y = v1;
                    *(float2*)(C + idx) = o;
                }
                if (epi >= 4)
                    *(__half2*)(Ch + idx) = __floats2half2_rn(v0, v1);
            }
        }
    }
}

__global__ __launch_bounds__(256, 2)
void gemm_h(const __half* __restrict__ A, const __half* __restrict__ B,
            float* __restrict__ C, int K, int N,
            const float* __restrict__ aux, int epi)
{
    extern __shared__ float smbuf[];
    uint32_t sbase = (uint32_t)__cvta_generic_to_shared(smbuf);
    gemm_core_h(A + (size_t)(blockIdx.y * 128) * K,
                B + (size_t)(blockIdx.x * 128) * K,
                C, nullptr, K, N, blockIdx.y * 128, blockIdx.x * 128, aux, epi, sbase);
}

__global__ __launch_bounds__(256, 2)
void gemm_qkv_h(const __half* __restrict__ A,
                const __half* __restrict__ qw, const __half* __restrict__ kw,
                const __half* __restrict__ vw,
                __half* __restrict__ qh, float* __restrict__ k, float* __restrict__ v,
                __half* __restrict__ kh, __half* __restrict__ vh)
{
    extern __shared__ float smbuf[];
    uint32_t sbase = (uint32_t)__cvta_generic_to_shared(smbuf);
    int bx = blockIdx.x;
    const __half* B; float* C; __half* Ch; int Nc, colb, epi;
    if (bx < 16)      { B = qw; C = nullptr; Ch = qh; Nc = HID; colb = bx * 128; epi = 4; }
    else if (bx < 20) { B = kw; C = k; Ch = kh; Nc = KVW; colb = (bx - 16) * 128; epi = 5; }
    else              { B = vw; C = v; Ch = vh; Nc = KVW; colb = (bx - 20) * 128; epi = 5; }
    gemm_core_h(A + (size_t)(blockIdx.y * 128) * HID,
                B + (size_t)colb * HID,
                C, Ch, HID, Nc, blockIdx.y * 128, colb, nullptr, epi, sbase);
}

// fused gate+up+silu: 128x64 of gate AND up, writes fp16 silu(g)*u
__global__ __launch_bounds__(256, 2)
void gemm_gateup_h(const __half* __restrict__ A, const __half* __restrict__ Gw,
                   const __half* __restrict__ Uw, __half* __restrict__ C)
{
    extern __shared__ float smbuf[];
    uint32_t sbase = (uint32_t)__cvta_generic_to_shared(smbuf);
    int tid = threadIdx.x, lane = tid & 31, warp = tid >> 5;
    int wm = (warp & 3) << 5;
    int wn = (warp >> 2) << 5;
    const __half* gA = A  + (size_t)(blockIdx.y * 128) * HID;
    const __half* gG = Gw + (size_t)(blockIdx.x * 64) * HID;
    const __half* gU = Uw + (size_t)(blockIdx.x * 64) * HID;

    float accg[2][4][4], accu[2][4][4];
    #pragma unroll
    for (int mi = 0; mi < 2; mi++)
        #pragma unroll
        for (int n = 0; n < 4; n++)
            #pragma unroll
            for (int j = 0; j < 4; j++) { accg[mi][n][j] = 0.f; accu[mi][n][j] = 0.f; }

    int a_r   = lane & 15;
    int a_kgo = lane >> 4;
    int b_r   = ((lane >> 4) << 3) + (lane & 7);
    int b_kgo = (lane >> 3) & 1;

    const int kTiles = HID >> 6;
    stage_agu_h(sbase,         gA,      gG,      gU,      HID, tid); cp_commit();
    stage_agu_h(sbase + 32768, gA + 64, gG + 64, gU + 64, HID, tid); cp_commit();
    cp_wait1();
    __syncthreads();

    int scur = 0, sfill = 2;
    for (int kt = 0; kt < kTiles; kt++) {
        if (kt + 2 < kTiles) {
            stage_agu_h(sbase + sfill * 32768, gA + (kt + 2) * 64, gG + (kt + 2) * 64,
                        gU + (kt + 2) * 64, HID, tid);
        }
        cp_commit();
        uint32_t sA = sbase + scur * 32768;
        uint32_t sG = sA + 16384;
        uint32_t sU = sA + 24576;
        #pragma unroll
        for (int kk = 0; kk < 4; kk++) {
            uint32_t afr[2][4], gfr[2][4], ufr[2][4];
            #pragma unroll
            for (int mi = 0; mi < 2; mi++) {
                int arow = wm + mi * 16 + a_r;
                int akg  = kk * 2 + a_kgo;
                uint32_t ad = sA + (uint32_t)(arow * 128 + ((akg ^ (arow & 7)) << 4));
                ldsm4(ad, afr[mi][0], afr[mi][1], afr[mi][2], afr[mi][3]);
            }
            #pragma unroll
            for (int nj = 0; nj < 2; nj++) {
                int brow = wn + nj * 16 + b_r;
                int bkg  = kk * 2 + b_kgo;
                uint32_t off = (uint32_t)(brow * 128 + ((bkg ^ (brow & 7)) << 4));
                ldsm4(sG + off, gfr[nj][0], gfr[nj][1], gfr[nj][2], gfr[nj][3]);
                ldsm4(sU + off, ufr[nj][0], ufr[nj][1], ufr[nj][2], ufr[nj][3]);
            }
            #pragma unroll
            for (int mi = 0; mi < 2; mi++)
                #pragma unroll
                for (int n = 0; n < 4; n++) {
                    mma_f16(accg[mi][n],
                            afr[mi][0], afr[mi][1], afr[mi][2], afr[mi][3],
                            gfr[n >> 1][(n & 1) * 2], gfr[n >> 1][(n & 1) * 2 + 1]);
                    mma_f16(accu[mi][n],
                            afr[mi][0], afr[mi][1], afr[mi][2], afr[mi][3],
                            ufr[n >> 1][(n & 1) * 2], ufr[n >> 1][(n & 1) * 2 + 1]);
                }
        }
        cp_wait1();
        __syncthreads();
        scur  = (scur  == 2) ? 0 : scur  + 1;
        sfill = (sfill == 2) ? 0 : sfill + 1;
    }

    int rb = blockIdx.y * 128 + wm + (lane >> 2);
    int cb = blockIdx.x * 64 + wn + ((lane & 3) << 1);
    #pragma unroll
    for (int mi = 0; mi < 2; mi++) {
        #pragma unroll
        for (int n = 0; n < 4; n++) {
            int cc = cb + n * 8;
            #pragma unroll
            for (int h = 0; h < 2; h++) {
                int rr = rb + mi * 16 + h * 8;
                float g0 = accg[mi][n][h * 2], g1 = accg[mi][n][h * 2 + 1];
                float u0 = accu[mi][n][h * 2], u1 = accu[mi][n][h * 2 + 1];
                float o0 = u0 * g0 / (1.f + __expf(-g0));
                float o1 = u1 * g1 / (1.f + __expf(-g1));
                *(__half2*)(C + (size_t)rr * INTER + cc) = __floats2half2_rn(o0, o1);
            }
        }
    }
}

// ---------------- fp16 flash attention: register-P, 3-stage KV, longest-first ----------------
#define SQ_OFF 0
#define KV_OFF 16384
#define ATT_SMEM (16384 + 3 * 32768)   // 112KB
__global__ __launch_bounds__(128)
void attn_h(const __half* __restrict__ Q, const __half* __restrict__ Kh,
            const __half* __restrict__ Vh, const int* __restrict__ cu,
            __half* __restrict__ O)
{
    extern __shared__ char smc[];
    uint32_t sb = (uint32_t)__cvta_generic_to_shared(smc);
    uint32_t sQb = sb + SQ_OFF;

    int h = blockIdx.x;
    int qt = (LQ / 64 - 1) - blockIdx.y;   // longest-first scheduling
    int kvh = h >> 2;
    int tid = threadIdx.x, lane = tid & 31, warp = tid >> 5;
    int wrow = warp << 4;

    // stage Q (fp16, 64 rows x 256B)
    #pragma unroll
    for (int i = 0; i < 8; i++) {
        int c = tid + i * 128;
        int row = c >> 4, g16 = c & 15;
        int chunk = g16 >> 3, g = g16 & 7;
        uint32_t off = (uint32_t)(chunk * 8192 + row * 128 + ((g ^ (row & 7)) << 4));
        cp16(sQb + off, Q + (size_t)(qt * 64 + row) * (NH * HD) + h * HD + g16 * 8);
    }

    int r0loc = wrow + (lane >> 2);
    int r1loc = r0loc + 8;
    int rg0 = qt * 64 + r0loc, rg1 = qt * 64 + r1loc;
    int ss0 = 0, ss1 = 0, segblk = 0;
    #pragma unroll
    for (int i = 0; i < 4; i++) {
        int c = cu[i];
        if (c <= rg0) ss0 = max(ss0, c);
        if (c <= rg1) ss1 = max(ss1, c);
        if (c <= qt * 64) segblk = max(segblk, c);
    }
    int kt0 = segblk >> 6;
    int nt = qt - kt0 + 1;

    int a_r   = lane & 15;
    int a_kgo = lane >> 4;
    int b_r   = ((lane >> 4) << 3) + (lane & 7);
    int b_kgo = (lane >> 3) & 1;
    int v_kr = (lane & 7) + (lane & 8);
    int v_dg = ((lane >> 4) & 1) * 8;

    float m0 = -1e30f, m1 = -1e30f, l0 = 0.f, l1 = 0.f;
    float o[16][4];
    #pragma unroll
    for (int f = 0; f < 16; f++)
        #pragma unroll
        for (int j = 0; j < 4; j++) o[f][j] = 0.f;

    // prologue: stage tile0 (group with Q), then tile1
    {
        uint32_t sd = sb + KV_OFF;
        #pragma unroll
        for (int i = 0; i < 8; i++) {
            int c = tid + i * 128;
            int row = c >> 4, g16 = c & 15;
            int chunk = g16 >> 3, g = g16 & 7;
            uint32_t off = (uint32_t)(chunk * 8192 + row * 128 + ((g ^ (row & 7)) << 4));
            size_t gidx = (size_t)(kt0 * 64 + row) * KVW + kvh * HD + g16 * 8;
            cp16(sd + off, Kh + gidx);
            cp16(sd + 16384 + off, Vh + gidx);
        }
    }
    cp_commit();
    if (nt > 1) {
        uint32_t sd = sb + KV_OFF + 32768;
        #pragma unroll
        for (int i = 0; i < 8; i++) {
            int c = tid + i * 128;
            int row = c >> 4, g16 = c & 15;
            int chunk = g16 >> 3, g = g16 & 7;
            uint32_t off = (uint32_t)(chunk * 8192 + row * 128 + ((g ^ (row & 7)) << 4));
            size_t gidx = (size_t)((kt0 + 1) * 64 + row) * KVW + kvh * HD + g16 * 8;
            cp16(sd + off, Kh + gidx);
            cp16(sd + 16384 + off, Vh + gidx);
        }
    }
    cp_commit();

    int scomp = 0, sfill = 2;
    for (int it = 0; it < nt; it++) {
        int kt = kt0 + it;
        cp_wait1();
        __syncthreads();
        if (it + 2 < nt) {
            uint32_t sd = sb + KV_OFF + sfill * 32768;
            #pragma unroll
            for (int i = 0; i < 8; i++) {
                int c = tid + i * 128;
                int row = c >> 4, g16 = c & 15;
                int chunk = g16 >> 3, g = g16 & 7;
                uint32_t off = (uint32_t)(chunk * 8192 + row * 128 + ((g ^ (row & 7)) << 4));
                size_t gidx = (size_t)((kt + 2) * 64 + row) * KVW + kvh * HD + g16 * 8;
                cp16(sd + off, Kh + gidx);
                cp16(sd + 16384 + off, Vh + gidx);
            }
        }
        cp_commit();
        uint32_t sKb = sb + KV_OFF + scomp * 32768;
        uint32_t sVb = sKb + 16384;

        float sc[8][4];
        #pragma unroll
        for (int f = 0; f < 8; f++)
            #pragma unroll
            for (int j = 0; j < 4; j++) sc[f][j] = 0.f;
        #pragma unroll
        for (int kk = 0; kk < 8; kk++) {
            int chunk = (kk >> 2) * 8192;
            int kin = (kk & 3) * 2;
            int arow = wrow + a_r;
            uint32_t ad = sQb + (uint32_t)(chunk + arow * 128 + (((kin + a_kgo) ^ (arow & 7)) << 4));
            uint32_t af0, af1, af2, af3;
            ldsm4(ad, af0, af1, af2, af3);
            #pragma unroll
            for (int nj = 0; nj < 4; nj++) {
                int brow = nj * 16 + b_r;
                uint32_t bd = sKb + (uint32_t)(chunk + brow * 128 + (((kin + b_kgo) ^ (brow & 7)) << 4));
                uint32_t b0, b1, b2, b3;
                ldsm4(bd, b0, b1, b2, b3);
                mma_f16(sc[nj * 2],     af0, af1, af2, af3, b0, b1);
                mma_f16(sc[nj * 2 + 1], af0, af1, af2, af3, b2, b3);
            }
        }

        const float SCALE = 0.08838834764831845f;
        float tm0 = -1e30f, tm1 = -1e30f;
        #pragma unroll
        for (int f = 0; f < 8; f++) {
            #pragma unroll
            for (int c2 = 0; c2 < 2; c2++) {
                int col = f * 8 + (lane & 3) * 2 + c2;
                int kg = kt * 64 + col;
                float v0 = (kg <= rg0 && kg >= ss0) ? sc[f][c2] * SCALE : -1e30f;
                float v1 = (kg <= rg1 && kg >= ss1) ? sc[f][2 + c2] * SCALE : -1e30f;
                sc[f][c2] = v0; sc[f][2 + c2] = v1;
                tm0 = fmaxf(tm0, v0); tm1 = fmaxf(tm1, v1);
            }
        }
        tm0 = fmaxf(tm0, __shfl_xor_sync(0xffffffffu, tm0, 1));
        tm0 = fmaxf(tm0, __shfl_xor_sync(0xffffffffu, tm0, 2));
        tm1 = fmaxf(tm1, __shfl_xor_sync(0xffffffffu, tm1, 1));
        tm1 = fmaxf(tm1, __shfl_xor_sync(0xffffffffu, tm1, 2));
        float mn0 = fmaxf(m0, tm0), mn1 = fmaxf(m1, tm1);
        float al0 = __expf(m0 - mn0), al1 = __expf(m1 - mn1);

        float ps0 = 0.f, ps1 = 0.f;
        #pragma unroll
        for (int f = 0; f < 8; f++) {
            float p00 = (sc[f][0] <= -1e29f) ? 0.f : __expf(sc[f][0] - mn0);
            float p01 = (sc[f][1] <= -1e29f) ? 0.f : __expf(sc[f][1] - mn0);
            float p10 = (sc[f][2] <= -1e29f) ? 0.f : __expf(sc[f][2] - mn1);
            float p11 = (sc[f][3] <= -1e29f) ? 0.f : __expf(sc[f][3] - mn1);
            ps0 += p00 + p01; ps1 += p10 + p11;
            sc[f][0] = p00; sc[f][1] = p01; sc[f][2] = p10; sc[f][3] = p11;
        }
        ps0 += __shfl_xor_sync(0xffffffffu, ps0, 1);
        ps0 += __shfl_xor_sync(0xffffffffu, ps0, 2);
        ps1 += __shfl_xor_sync(0xffffffffu, ps1, 1);
        ps1 += __shfl_xor_sync(0xffffffffu, ps1, 2);
        l0 = l0 * al0 + ps0; l1 = l1 * al1 + ps1;
        m0 = mn0; m1 = mn1;
        #pragma unroll
        for (int f = 0; f < 16; f++) {
            o[f][0] *= al0; o[f][1] *= al0; o[f][2] *= al1; o[f][3] *= al1;
        }

        // pack P into A-fragments directly (FA2 register identity)
        uint32_t pp[4][4];
        #pragma unroll
        for (int t = 0; t < 4; t++) {
            __half2 ha = __floats2half2_rn(sc[2 * t][0],     sc[2 * t][1]);
            __half2 hb = __floats2half2_rn(sc[2 * t][2],     sc[2 * t][3]);
            __half2 hc = __floats2half2_rn(sc[2 * t + 1][0], sc[2 * t + 1][1]);
            __half2 hd = __floats2half2_rn(sc[2 * t + 1][2], sc[2 * t + 1][3]);
            pp[t][0] = *(const uint32_t*)&ha;
            pp[t][1] = *(const uint32_t*)&hb;
            pp[t][2] = *(const uint32_t*)&hc;
            pp[t][3] = *(const uint32_t*)&hd;
        }

        // O += P @ V
        #pragma unroll
        for (int kk = 0; kk < 4; kk++) {
            int kr = kk * 16 + v_kr;
            #pragma unroll
            for (int t = 0; t < 8; t++) {
                int dcol = t * 16 + v_dg;
                int chunk = dcol >> 6, g = (dcol & 63) >> 3;
                uint32_t bd = sVb + (uint32_t)(chunk * 8192 + kr * 128 + ((g ^ (kr & 7)) << 4));
                uint32_t v0, v1, v2, v3;
                ldsm4t(bd, v0, v1, v2, v3);
                mma_f16(o[2 * t],     pp[kk][0], pp[kk][1], pp[kk][2], pp[kk][3], v0, v1);
                mma_f16(o[2 * t + 1], pp[kk][0], pp[kk][1], pp[kk][2], pp[kk][3], v2, v3);
            }
        }
        scomp = (scomp == 2) ? 0 : scomp + 1;
        sfill = (sfill == 2) ? 0 : sfill + 1;
    }

    float inv0 = 1.f / l0, inv1 = 1.f / l1;
    #pragma unroll
    for (int f = 0; f < 16; f++) {
        int col = f * 8 + (lane & 3) * 2;
        *(__half2*)(O + (size_t)rg0 * (NH * HD) + h * HD + col) =
            __floats2half2_rn(o[f][0] * inv0, o[f][1] * inv0);
        *(__half2*)(O + (size_t)rg1 * (NH * HD) + h * HD + col) =
            __floats2half2_rn(o[f][2] * inv1, o[f][3] * inv1);
    }
}

// ---------------- launcher ----------------
extern "C" void kernel_launch(void* const* d_in, const int* in_sizes, int n_in,
                              void* d_out, int out_size)
{
    const float* hs  = (const float*)d_in[0];
    const int*   cu  = (const int*)  d_in[1];
    const float* ln1 = (const float*)d_in[2];
    const float* ln2 = (const float*)d_in[3];
    const float* qw  = (const float*)d_in[4];
    const float* kw  = (const float*)d_in[5];
    const float* vw  = (const float*)d_in[6];
    const float* ow  = (const float*)d_in[7];
    const float* gw  = (const float*)d_in[8];
    const float* uw  = (const float*)d_in[9];
    const float* dw  = (const float*)d_in[10];

    float* out_hidden = (float*)d_out;
    float* out_key    = out_hidden + (size_t)LQ * HID;
    float* out_val    = out_key    + (size_t)LQ * KVW;

    __half *p_normed, *p_qh, *p_kh, *p_vh, *p_attn, *p_n2, *p_act;
    float *p_h1;
    __half *rw_q, *rw_k, *rw_v, *rw_o, *rw_g, *rw_u, *rw_d;
    cudaGetSymbolAddress((void**)&p_normed, g_normed);
    cudaGetSymbolAddress((void**)&p_qh,     g_qh);
    cudaGetSymbolAddress((void**)&p_kh,     g_kh);
    cudaGetSymbolAddress((void**)&p_vh,     g_vh);
    cudaGetSymbolAddress((void**)&p_attn,   g_attn);
    cudaGetSymbolAddress((void**)&p_h1,     g_h1);
    cudaGetSymbolAddress((void**)&p_n2,     g_n2);
    cudaGetSymbolAddress((void**)&p_act,    g_act);
    cudaGetSymbolAddress((void**)&rw_q, w_q);
    cudaGetSymbolAddress((void**)&rw_k, w_k);
    cudaGetSymbolAddress((void**)&rw_v, w_v);
    cudaGetSymbolAddress((void**)&rw_o, w_o);
    cudaGetSymbolAddress((void**)&rw_g, w_g);
    cudaGetSymbolAddress((void**)&rw_u, w_u);
    cudaGetSymbolAddress((void**)&rw_d, w_d);

    cudaFuncSetAttribute(attn_h, cudaFuncAttributeMaxDynamicSharedMemorySize, ATT_SMEM);
    int gemm_smem = 3 * 32768;  // 96KB
    cudaFuncSetAttribute(gemm_h,        cudaFuncAttributeMaxDynamicSharedMemorySize, gemm_smem);
    cudaFuncSetAttribute(gemm_qkv_h,    cudaFuncAttributeMaxDynamicSharedMemorySize, gemm_smem);
    cudaFuncSetAttribute(gemm_gateup_h, cudaFuncAttributeMaxDynamicSharedMemorySize, gemm_smem);

    // side stream + events (host objects; created per call, left for harness teardown)
    cudaStream_t s2;
    cudaStreamCreateWithFlags(&s2, cudaStreamNonBlocking);
    cudaEvent_t evFork, evJoin;
    cudaEventCreateWithFlags(&evFork, cudaEventDisableTiming);
    cudaEventCreateWithFlags(&evJoin, cudaEventDisableTiming);

    // 0a) convert q/k/v weights (needed immediately) on main stream
    convert_qkv<<<dim3(512, 3), 256>>>(qw, kw, vw, rw_q, rw_k, rw_v);

    // 1) ln1 (fp16 output)
    rmsnorm_h<<<LQ, 512>>>(hs, ln1, p_normed);
    // 2) fused QKV: Q fp16 ; K,V fp32 into d_out AND fp16 copies
    gemm_qkv_h<<<dim3(24, LQ / 128), 256, gemm_smem>>>(p_normed, rw_q, rw_k, rw_v,
                                                       p_qh, out_key, out_val, p_kh, p_vh);
    // fork AFTER QKV: conversion overlaps attention (where RF allows coresidency),
    // not the RF-saturated QKV GEMM
    cudaEventRecord(evFork, 0);
    cudaStreamWaitEvent(s2, evFork, 0);
    convert_ogud<<<dim3(1024, 4), 256, 0, s2>>>(ow, gw, uw, dw, rw_o, rw_g, rw_u, rw_d);
    cudaEventRecord(evJoin, s2);

    // 3) fp16 flash attention (register-P, 3-stage KV, longest-first)
    attn_h<<<dim3(NH, LQ / 64), 128, ATT_SMEM>>>(p_qh, p_kh, p_vh, cu, p_attn);

    // join: o/g/u/d fp16 weights must be ready past this point
    cudaStreamWaitEvent(0, evJoin, 0);

    // 4) O-proj + residual (fp32 out)
    gemm_h<<<dim3(HID / 128, LQ / 128), 256, gemm_smem>>>(p_attn, rw_o, p_h1, HID, HID, hs, 1);
    // 5) ln2 (fp16 output)
    rmsnorm_h<<<LQ, 512>>>(p_h1, ln2, p_n2);
    // 6) fused gate+up+silu (fp16 output)
    gemm_gateup_h<<<dim3(INTER / 64, LQ / 128), 256, gemm_smem>>>(p_n2, rw_g, rw_u, p_act);
    // 7) down + residual -> output hidden
    gemm_h<<<dim3(HID / 128, LQ / 128), 256, gemm_smem>>>(p_act, rw_d, out_hidden, INTER, HID, p_h1, 1);
}

// round 17
// speedup vs baseline: 1.0320x; 1.0320x over previous
#include <cuda_runtime.h>
#include <cuda_fp16.h>
#include <math.h>
#include <stdint.h>

#define LQ 2048
#define HID 2048
#define NH 16
#define NKV 4
#define HD 128
#define INTER 8192
#define KVW (NKV*HD)   // 512

// ---------------- scratch (device globals; no allocation allowed) ----------------
__device__ __half g_normed[LQ*HID];
__device__ __half g_qh[LQ*HID];
__device__ __half g_kh[LQ*KVW];
__device__ __half g_vh[LQ*KVW];
__device__ __half g_attn[LQ*HID];
__device__ float  g_h1[LQ*HID];
__device__ __half g_n2[LQ*HID];
__device__ __half g_act[LQ*INTER];
// fp16 weight copies
__device__ __half w_q[HID*HID];
__device__ __half w_k[KVW*HID];
__device__ __half w_v[KVW*HID];
__device__ __half w_o[HID*HID];
__device__ __half w_g[INTER*HID];
__device__ __half w_u[INTER*HID];
__device__ __half w_d[HID*INTER];

// ---------------- PTX helpers ----------------
__device__ __forceinline__ void cp16(uint32_t dst, const void* src)
{
    asm volatile("cp.async.cg.shared.global [%0], [%1], 16;\n" :: "r"(dst), "l"(src));
}
__device__ __forceinline__ void cp_commit() { asm volatile("cp.async.commit_group;\n"); }
__device__ __forceinline__ void cp_wait1()  { asm volatile("cp.async.wait_group 1;\n"); }
__device__ __forceinline__ void cp_wait0()  { asm volatile("cp.async.wait_group 0;\n"); }

__device__ __forceinline__ void ldsm4(uint32_t addr, uint32_t& r0, uint32_t& r1,
                                      uint32_t& r2, uint32_t& r3)
{
    asm volatile("ldmatrix.sync.aligned.m8n8.x4.shared.b16 {%0,%1,%2,%3}, [%4];\n"
                 : "=r"(r0), "=r"(r1), "=r"(r2), "=r"(r3) : "r"(addr));
}
__device__ __forceinline__ void ldsm4t(uint32_t addr, uint32_t& r0, uint32_t& r1,
                                       uint32_t& r2, uint32_t& r3)
{
    asm volatile("ldmatrix.sync.aligned.m8n8.x4.trans.shared.b16 {%0,%1,%2,%3}, [%4];\n"
                 : "=r"(r0), "=r"(r1), "=r"(r2), "=r"(r3) : "r"(addr));
}
__device__ __forceinline__ void mma_f16(float* d, uint32_t a0, uint32_t a1,
                                        uint32_t a2, uint32_t a3,
                                        uint32_t b0, uint32_t b1)
{
    asm volatile("mma.sync.aligned.m16n8k16.row.col.f32.f16.f16.f32 "
                 "{%0,%1,%2,%3},{%4,%5,%6,%7},{%8,%9},{%0,%1,%2,%3};\n"
                 : "+f"(d[0]), "+f"(d[1]), "+f"(d[2]), "+f"(d[3])
                 : "r"(a0), "r"(a1), "r"(a2), "r"(a3), "r"(b0), "r"(b1));
}

// ---------------- weight conversion ----------------
__device__ __forceinline__ void conv_seg(const float* s, __half* d, int n)
{
    int n8 = n >> 3;
    const float4* s4p = (const float4*)s;
    uint4* d4p = (uint4*)d;
    int stride = gridDim.x * blockDim.x;
    for (int i = blockIdx.x * blockDim.x + threadIdx.x; i < n8; i += stride) {
        float4 a = s4p[2 * i];
        float4 b = s4p[2 * i + 1];
        __half2 h0 = __floats2half2_rn(a.x, a.y);
        __half2 h1 = __floats2half2_rn(a.z, a.w);
        __half2 h2 = __floats2half2_rn(b.x, b.y);
        __half2 h3 = __floats2half2_rn(b.z, b.w);
        uint4 o;
        o.x = *(const uint32_t*)&h0; o.y = *(const uint32_t*)&h1;
        o.z = *(const uint32_t*)&h2; o.w = *(const uint32_t*)&h3;
        d4p[i] = o;
    }
}
__global__ void convert_qkv(const float* __restrict__ sq, const float* __restrict__ sk,
                            const float* __restrict__ sv,
                            __half* __restrict__ dq, __half* __restrict__ dk,
                            __half* __restrict__ dv)
{
    int seg = blockIdx.y;
    if (seg == 0) conv_seg(sq, dq, HID * HID);
    else if (seg == 1) conv_seg(sk, dk, KVW * HID);
    else conv_seg(sv, dv, KVW * HID);
}
__global__ void convert_o(const float* __restrict__ so, __half* __restrict__ dmo)
{
    conv_seg(so, dmo, HID * HID);
}
__global__ void convert_gu(const float* __restrict__ sg, const float* __restrict__ su,
                           __half* __restrict__ dmg, __half* __restrict__ dmu)
{
    if (blockIdx.y == 0) conv_seg(sg, dmg, INTER * HID);
    else conv_seg(su, dmu, INTER * HID);
}
__global__ void convert_d(const float* __restrict__ sd, __half* __restrict__ dmd)
{
    conv_seg(sd, dmd, HID * INTER);
}

// ---------------- RMSNorm (vectorized, fp16 output) ----------------
__global__ void rmsnorm_h(const float* __restrict__ x, const float* __restrict__ w,
                          __half* __restrict__ o)
{
    int row = blockIdx.x;
    int tid = threadIdx.x;           // 512 threads; 512*4 = 2048 = HID
    const float4* xr = (const float4*)(x + (size_t)row * HID);
    float4 v = xr[tid];
    float ss = v.x * v.x + v.y * v.y + v.z * v.z + v.w * v.w;
    #pragma unroll
    for (int off = 16; off; off >>= 1) ss += __shfl_xor_sync(0xffffffffu, ss, off);
    __shared__ float red[16];
    __shared__ float sscale;
    if ((tid & 31) == 0) red[tid >> 5] = ss;
    __syncthreads();
    if (tid == 0) {
        float t = 0.f;
        #pragma unroll
        for (int i = 0; i < 16; i++) t += red[i];
        sscale = rsqrtf(t / (float)HID + 1e-6f);
    }
    __syncthreads();
    float scale = sscale;
    float4 wv = ((const float4*)w)[tid];
    __half2 h0 = __floats2half2_rn(v.x * scale * wv.x, v.y * scale * wv.y);
    __half2 h1 = __floats2half2_rn(v.z * scale * wv.z, v.w * scale * wv.w);
    uint2 ov; ov.x = *(const uint32_t*)&h0; ov.y = *(const uint32_t*)&h1;
    ((uint2*)(o + (size_t)row * HID))[tid] = ov;
}

// ---------------- fp16 staging: 128 rows x 64 halves (128B/row) per matrix ----------------
__device__ __forceinline__ void stage_ab_h(uint32_t s, const __half* gA, const __half* gB,
                                           int K, int tid)
{
    #pragma unroll
    for (int i = 0; i < 4; i++) {
        int c = tid + i * 256;
        int row = c >> 3, g = c & 7;
        uint32_t off = (uint32_t)(row * 128 + ((g ^ (row & 7)) << 4));
        cp16(s + off,         gA + (size_t)row * K + g * 8);
        cp16(s + 16384 + off, gB + (size_t)row * K + g * 8);
    }
}
__device__ __forceinline__ void stage_agu_h(uint32_t s, const __half* gA, const __half* gG,
                                            const __half* gU, int K, int tid)
{
    #pragma unroll
    for (int i = 0; i < 4; i++) {
        int c = tid + i * 256;
        int row = c >> 3, g = c & 7;
        uint32_t off = (uint32_t)(row * 128 + ((g ^ (row & 7)) << 4));
        cp16(s + off, gA + (size_t)row * K + g * 8);
    }
    #pragma unroll
    for (int i = 0; i < 2; i++) {
        int c = tid + i * 256;
        int row = c >> 3, g = c & 7;
        uint32_t off = (uint32_t)(row * 128 + ((g ^ (row & 7)) << 4));
        cp16(s + 16384 + off, gG + (size_t)row * K + g * 8);
        cp16(s + 24576 + off, gU + (size_t)row * K + g * 8);
    }
}

// ---------------- fp16 GEMM core: 128x128 block, k-tile 64, 3-stage ----------------
// epi 0: C=acc(f32) ; 1: C=acc+aux(f32) ; 4: Ch=half(acc) ; 5: C=f32 AND Ch=half
__device__ __forceinline__ void gemm_core_h(
    const __half* __restrict__ gA, const __half* __restrict__ gB,
    float* __restrict__ C, __half* __restrict__ Ch,
    int K, int Nc, int crow0, int ccol0,
    const float* __restrict__ aux, int epi, uint32_t sbase)
{
    int tid = threadIdx.x, lane = tid & 31, warp = tid >> 5;
    int wm = (warp & 3) << 5;
    int wn = (warp >> 2) << 6;

    float acc[2][8][4];
    #pragma unroll
    for (int mi = 0; mi < 2; mi++)
        #pragma unroll
        for (int n = 0; n < 8; n++)
            #pragma unroll
            for (int j = 0; j < 4; j++) acc[mi][n][j] = 0.f;

    int a_r   = lane & 15;
    int a_kgo = lane >> 4;
    int b_r   = ((lane >> 4) << 3) + (lane & 7);
    int b_kgo = (lane >> 3) & 1;

    int kTiles = K >> 6;
    stage_ab_h(sbase,         gA,      gB,      K, tid); cp_commit();
    stage_ab_h(sbase + 32768, gA + 64, gB + 64, K, tid); cp_commit();
    cp_wait1();
    __syncthreads();

    int scur = 0, sfill = 2;   // rotating stage indices
    for (int kt = 0; kt < kTiles; kt++) {
        if (kt + 2 < kTiles) {
            stage_ab_h(sbase + sfill * 32768, gA + (kt + 2) * 64, gB + (kt + 2) * 64, K, tid);
        }
        cp_commit();
        uint32_t sA = sbase + scur * 32768;
        uint32_t sB = sA + 16384;
        #pragma unroll
        for (int kk = 0; kk < 4; kk++) {
            uint32_t afr[2][4], bfr[4][4];
            #pragma unroll
            for (int mi = 0; mi < 2; mi++) {
                int arow = wm + mi * 16 + a_r;
                int akg  = kk * 2 + a_kgo;
                uint32_t ad = sA + (uint32_t)(arow * 128 + ((akg ^ (arow & 7)) << 4));
                ldsm4(ad, afr[mi][0], afr[mi][1], afr[mi][2], afr[mi][3]);
            }
            #pragma unroll
            for (int nj = 0; nj < 4; nj++) {
                int brow = wn + nj * 16 + b_r;
                int bkg  = kk * 2 + b_kgo;
                uint32_t bd = sB + (uint32_t)(brow * 128 + ((bkg ^ (brow & 7)) << 4));
                ldsm4(bd, bfr[nj][0], bfr[nj][1], bfr[nj][2], bfr[nj][3]);
            }
            #pragma unroll
            for (int mi = 0; mi < 2; mi++)
                #pragma unroll
                for (int n = 0; n < 8; n++)
                    mma_f16(acc[mi][n],
                            afr[mi][0], afr[mi][1], afr[mi][2], afr[mi][3],
                            bfr[n >> 1][(n & 1) * 2], bfr[n >> 1][(n & 1) * 2 + 1]);
        }
        cp_wait1();
        __syncthreads();
        scur  = (scur  == 2) ? 0 : scur  + 1;
        sfill = (sfill == 2) ? 0 : sfill + 1;
    }

    int rb = crow0 + wm + (lane >> 2);
    int cb = ccol0 + wn + ((lane & 3) << 1);
    #pragma unroll
    for (int mi = 0; mi < 2; mi++) {
        #pragma unroll
        for (int n = 0; n < 8; n++) {
            int cc = cb + n * 8;
            #pragma unroll
            for (int h = 0; h < 2; h++) {
                int rr = rb + mi * 16 + h * 8;
                size_t idx = (size_t)rr * Nc + cc;
                float v0 = acc[mi][n][h * 2], v1 = acc[mi][n][h * 2 + 1];
                if (epi == 1) {
                    float2 x = *(const float2*)(aux + idx);
                    v0 += x.x; v1 += x.y;
                }
                if (epi != 4) {
                    float2 o; o.x = v0; o.y = v1;
                    *(float2*)(C + idx) = o;
                }
                if (epi >= 4)
                    *(__half2*)(Ch + idx) = __floats2half2_rn(v0, v1);
            }
        }
    }
}

__global__ __launch_bounds__(256, 2)
void gemm_h(const __half* __restrict__ A, const __half* __restrict__ B,
            float* __restrict__ C, int K, int N,
            const float* __restrict__ aux, int epi)
{
    extern __shared__ float smbuf[];
    uint32_t sbase = (uint32_t)__cvta_generic_to_shared(smbuf);
    gemm_core_h(A + (size_t)(blockIdx.y * 128) * K,
                B + (size_t)(blockIdx.x * 128) * K,
                C, nullptr, K, N, blockIdx.y * 128, blockIdx.x * 128, aux, epi, sbase);
}

__global__ __launch_bounds__(256, 2)
void gemm_qkv_h(const __half* __restrict__ A,
                const __half* __restrict__ qw, const __half* __restrict__ kw,
                const __half* __restrict__ vw,
                __half* __restrict__ qh, float* __restrict__ k, float* __restrict__ v,
                __half* __restrict__ kh, __half* __restrict__ vh)
{
    extern __shared__ float smbuf[];
    uint32_t sbase = (uint32_t)__cvta_generic_to_shared(smbuf);
    int bx = blockIdx.x;
    const __half* B; float* C; __half* Ch; int Nc, colb, epi;
    if (bx < 16)      { B = qw; C = nullptr; Ch = qh; Nc = HID; colb = bx * 128; epi = 4; }
    else if (bx < 20) { B = kw; C = k; Ch = kh; Nc = KVW; colb = (bx - 16) * 128; epi = 5; }
    else              { B = vw; C = v; Ch = vh; Nc = KVW; colb = (bx - 20) * 128; epi = 5; }
    gemm_core_h(A + (size_t)(blockIdx.y * 128) * HID,
                B + (size_t)colb * HID,
                C, Ch, HID, Nc, blockIdx.y * 128, colb, nullptr, epi, sbase);
}

// fused gate+up+silu: 128x64 of gate AND up, writes fp16 silu(g)*u
__global__ __launch_bounds__(256, 2)
void gemm_gateup_h(const __half* __restrict__ A, const __half* __restrict__ Gw,
                   const __half* __restrict__ Uw, __half* __restrict__ C)
{
    extern __shared__ float smbuf[];
    uint32_t sbase = (uint32_t)__cvta_generic_to_shared(smbuf);
    int tid = threadIdx.x, lane = tid & 31, warp = tid >> 5;
    int wm = (warp & 3) << 5;
    int wn = (warp >> 2) << 5;
    const __half* gA = A  + (size_t)(blockIdx.y * 128) * HID;
    const __half* gG = Gw + (size_t)(blockIdx.x * 64) * HID;
    const __half* gU = Uw + (size_t)(blockIdx.x * 64) * HID;

    float accg[2][4][4], accu[2][4][4];
    #pragma unroll
    for (int mi = 0; mi < 2; mi++)
        #pragma unroll
        for (int n = 0; n < 4; n++)
            #pragma unroll
            for (int j = 0; j < 4; j++) { accg[mi][n][j] = 0.f; accu[mi][n][j] = 0.f; }

    int a_r   = lane & 15;
    int a_kgo = lane >> 4;
    int b_r   = ((lane >> 4) << 3) + (lane & 7);
    int b_kgo = (lane >> 3) & 1;

    const int kTiles = HID >> 6;
    stage_agu_h(sbase,         gA,      gG,      gU,      HID, tid); cp_commit();
    stage_agu_h(sbase + 32768, gA + 64, gG + 64, gU + 64, HID, tid); cp_commit();
    cp_wait1();
    __syncthreads();

    int scur = 0, sfill = 2;
    for (int kt = 0; kt < kTiles; kt++) {
        if (kt + 2 < kTiles) {
            stage_agu_h(sbase + sfill * 32768, gA + (kt + 2) * 64, gG + (kt + 2) * 64,
                        gU + (kt + 2) * 64, HID, tid);
        }
        cp_commit();
        uint32_t sA = sbase + scur * 32768;
        uint32_t sG = sA + 16384;
        uint32_t sU = sA + 24576;
        #pragma unroll
        for (int kk = 0; kk < 4; kk++) {
            uint32_t afr[2][4], gfr[2][4], ufr[2][4];
            #pragma unroll
            for (int mi = 0; mi < 2; mi++) {
                int arow = wm + mi * 16 + a_r;
                int akg  = kk * 2 + a_kgo;
                uint32_t ad = sA + (uint32_t)(arow * 128 + ((akg ^ (arow & 7)) << 4));
                ldsm4(ad, afr[mi][0], afr[mi][1], afr[mi][2], afr[mi][3]);
            }
            #pragma unroll
            for (int nj = 0; nj < 2; nj++) {
                int brow = wn + nj * 16 + b_r;
                int bkg  = kk * 2 + b_kgo;
                uint32_t off = (uint32_t)(brow * 128 + ((bkg ^ (brow & 7)) << 4));
                ldsm4(sG + off, gfr[nj][0], gfr[nj][1], gfr[nj][2], gfr[nj][3]);
                ldsm4(sU + off, ufr[nj][0], ufr[nj][1], ufr[nj][2], ufr[nj][3]);
            }
            #pragma unroll
            for (int mi = 0; mi < 2; mi++)
                #pragma unroll
                for (int n = 0; n < 4; n++) {
                    mma_f16(accg[mi][n],
                            afr[mi][0], afr[mi][1], afr[mi][2], afr[mi][3],
                            gfr[n >> 1][(n & 1) * 2], gfr[n >> 1][(n & 1) * 2 + 1]);
                    mma_f16(accu[mi][n],
                            afr[mi][0], afr[mi][1], afr[mi][2], afr[mi][3],
                            ufr[n >> 1][(n & 1) * 2], ufr[n >> 1][(n & 1) * 2 + 1]);
                }
        }
        cp_wait1();
        __syncthreads();
        scur  = (scur  == 2) ? 0 : scur  + 1;
        sfill = (sfill == 2) ? 0 : sfill + 1;
    }

    int rb = blockIdx.y * 128 + wm + (lane >> 2);
    int cb = blockIdx.x * 64 + wn + ((lane & 3) << 1);
    #pragma unroll
    for (int mi = 0; mi < 2; mi++) {
        #pragma unroll
        for (int n = 0; n < 4; n++) {
            int cc = cb + n * 8;
            #pragma unroll
            for (int h = 0; h < 2; h++) {
                int rr = rb + mi * 16 + h * 8;
                float g0 = accg[mi][n][h * 2], g1 = accg[mi][n][h * 2 + 1];
                float u0 = accu[mi][n][h * 2], u1 = accu[mi][n][h * 2 + 1];
                float o0 = u0 * g0 / (1.f + __expf(-g0));
                float o1 = u1 * g1 / (1.f + __expf(-g1));
                *(__half2*)(C + (size_t)rr * INTER + cc) = __floats2half2_rn(o0, o1);
            }
        }
    }
}

// ---------------- fp16 flash attention: register-P, 3-stage KV, longest-first ----------------
#define SQ_OFF 0
#define KV_OFF 16384
#define ATT_SMEM (16384 + 3 * 32768)   // 112KB
__global__ __launch_bounds__(128)
void attn_h(const __half* __restrict__ Q, const __half* __restrict__ Kh,
            const __half* __restrict__ Vh, const int* __restrict__ cu,
            __half* __restrict__ O)
{
    extern __shared__ char smc[];
    uint32_t sb = (uint32_t)__cvta_generic_to_shared(smc);
    uint32_t sQb = sb + SQ_OFF;

    int h = blockIdx.x;
    int qt = (LQ / 64 - 1) - blockIdx.y;   // longest-first scheduling
    int kvh = h >> 2;
    int tid = threadIdx.x, lane = tid & 31, warp = tid >> 5;
    int wrow = warp << 4;

    #pragma unroll
    for (int i = 0; i < 8; i++) {
        int c = tid + i * 128;
        int row = c >> 4, g16 = c & 15;
        int chunk = g16 >> 3, g = g16 & 7;
        uint32_t off = (uint32_t)(chunk * 8192 + row * 128 + ((g ^ (row & 7)) << 4));
        cp16(sQb + off, Q + (size_t)(qt * 64 + row) * (NH * HD) + h * HD + g16 * 8);
    }

    int r0loc = wrow + (lane >> 2);
    int r1loc = r0loc + 8;
    int rg0 = qt * 64 + r0loc, rg1 = qt * 64 + r1loc;
    int ss0 = 0, ss1 = 0, segblk = 0;
    #pragma unroll
    for (int i = 0; i < 4; i++) {
        int c = cu[i];
        if (c <= rg0) ss0 = max(ss0, c);
        if (c <= rg1) ss1 = max(ss1, c);
        if (c <= qt * 64) segblk = max(segblk, c);
    }
    int kt0 = segblk >> 6;
    int nt = qt - kt0 + 1;

    int a_r   = lane & 15;
    int a_kgo = lane >> 4;
    int b_r   = ((lane >> 4) << 3) + (lane & 7);
    int b_kgo = (lane >> 3) & 1;
    int v_kr = (lane & 7) + (lane & 8);
    int v_dg = ((lane >> 4) & 1) * 8;

    float m0 = -1e30f, m1 = -1e30f, l0 = 0.f, l1 = 0.f;
    float o[16][4];
    #pragma unroll
    for (int f = 0; f < 16; f++)
        #pragma unroll
        for (int j = 0; j < 4; j++) o[f][j] = 0.f;

    {
        uint32_t sd = sb + KV_OFF;
        #pragma unroll
        for (int i = 0; i < 8; i++) {
            int c = tid + i * 128;
            int row = c >> 4, g16 = c & 15;
            int chunk = g16 >> 3, g = g16 & 7;
            uint32_t off = (uint32_t)(chunk * 8192 + row * 128 + ((g ^ (row & 7)) << 4));
            size_t gidx = (size_t)(kt0 * 64 + row) * KVW + kvh * HD + g16 * 8;
            cp16(sd + off, Kh + gidx);
            cp16(sd + 16384 + off, Vh + gidx);
        }
    }
    cp_commit();
    if (nt > 1) {
        uint32_t sd = sb + KV_OFF + 32768;
        #pragma unroll
        for (int i = 0; i < 8; i++) {
            int c = tid + i * 128;
            int row = c >> 4, g16 = c & 15;
            int chunk = g16 >> 3, g = g16 & 7;
            uint32_t off = (uint32_t)(chunk * 8192 + row * 128 + ((g ^ (row & 7)) << 4));
            size_t gidx = (size_t)((kt0 + 1) * 64 + row) * KVW + kvh * HD + g16 * 8;
            cp16(sd + off, Kh + gidx);
            cp16(sd + 16384 + off, Vh + gidx);
        }
    }
    cp_commit();

    int scomp = 0, sfill = 2;
    for (int it = 0; it < nt; it++) {
        int kt = kt0 + it;
        cp_wait1();
        __syncthreads();
        if (it + 2 < nt) {
            uint32_t sd = sb + KV_OFF + sfill * 32768;
            #pragma unroll
            for (int i = 0; i < 8; i++) {
                int c = tid + i * 128;
                int row = c >> 4, g16 = c & 15;
                int chunk = g16 >> 3, g = g16 & 7;
                uint32_t off = (uint32_t)(chunk * 8192 + row * 128 + ((g ^ (row & 7)) << 4));
                size_t gidx = (size_t)((kt + 2) * 64 + row) * KVW + kvh * HD + g16 * 8;
                cp16(sd + off, Kh + gidx);
                cp16(sd + 16384 + off, Vh + gidx);
            }
        }
        cp_commit();
        uint32_t sKb = sb + KV_OFF + scomp * 32768;
        uint32_t sVb = sKb + 16384;

        float sc[8][4];
        #pragma unroll
        for (int f = 0; f < 8; f++)
            #pragma unroll
            for (int j = 0; j < 4; j++) sc[f][j] = 0.f;
        #pragma unroll
        for (int kk = 0; kk < 8; kk++) {
            int chunk = (kk >> 2) * 8192;
            int kin = (kk & 3) * 2;
            int arow = wrow + a_r;
            uint32_t ad = sQb + (uint32_t)(chunk + arow * 128 + (((kin + a_kgo) ^ (arow & 7)) << 4));
            uint32_t af0, af1, af2, af3;
            ldsm4(ad, af0, af1, af2, af3);
            #pragma unroll
            for (int nj = 0; nj < 4; nj++) {
                int brow = nj * 16 + b_r;
                uint32_t bd = sKb + (uint32_t)(chunk + brow * 128 + (((kin + b_kgo) ^ (brow & 7)) << 4));
                uint32_t b0, b1, b2, b3;
                ldsm4(bd, b0, b1, b2, b3);
                mma_f16(sc[nj * 2],     af0, af1, af2, af3, b0, b1);
                mma_f16(sc[nj * 2 + 1], af0, af1, af2, af3, b2, b3);
            }
        }

        const float SCALE = 0.08838834764831845f;
        float tm0 = -1e30f, tm1 = -1e30f;
        #pragma unroll
        for (int f = 0; f < 8; f++) {
            #pragma unroll
            for (int c2 = 0; c2 < 2; c2++) {
                int col = f * 8 + (lane & 3) * 2 + c2;
                int kg = kt * 64 + col;
                float v0 = (kg <= rg0 && kg >= ss0) ? sc[f][c2] * SCALE : -1e30f;
                float v1 = (kg <= rg1 && kg >= ss1) ? sc[f][2 + c2] * SCALE : -1e30f;
                sc[f][c2] = v0; sc[f][2 + c2] = v1;
                tm0 = fmaxf(tm0, v0); tm1 = fmaxf(tm1, v1);
            }
        }
        tm0 = fmaxf(tm0, __shfl_xor_sync(0xffffffffu, tm0, 1));
        tm0 = fmaxf(tm0, __shfl_xor_sync(0xffffffffu, tm0, 2));
        tm1 = fmaxf(tm1, __shfl_xor_sync(0xffffffffu, tm1, 1));
        tm1 = fmaxf(tm1, __shfl_xor_sync(0xffffffffu, tm1, 2));
        float mn0 = fmaxf(m0, tm0), mn1 = fmaxf(m1, tm1);
        float al0 = __expf(m0 - mn0), al1 = __expf(m1 - mn1);

        float ps0 = 0.f, ps1 = 0.f;
        #pragma unroll
        for (int f = 0; f < 8; f++) {
            float p00 = (sc[f][0] <= -1e29f) ? 0.f : __expf(sc[f][0] - mn0);
            float p01 = (sc[f][1] <= -1e29f) ? 0.f : __expf(sc[f][1] - mn0);
            float p10 = (sc[f][2] <= -1e29f) ? 0.f : __expf(sc[f][2] - mn1);
            float p11 = (sc[f][3] <= -1e29f) ? 0.f : __expf(sc[f][3] - mn1);
            ps0 += p00 + p01; ps1 += p10 + p11;
            sc[f][0] = p00; sc[f][1] = p01; sc[f][2] = p10; sc[f][3] = p11;
        }
        ps0 += __shfl_xor_sync(0xffffffffu, ps0, 1);
        ps0 += __shfl_xor_sync(0xffffffffu, ps0, 2);
        ps1 += __shfl_xor_sync(0xffffffffu, ps1, 1);
        ps1 += __shfl_xor_sync(0xffffffffu, ps1, 2);
        l0 = l0 * al0 + ps0; l1 = l1 * al1 + ps1;
        m0 = mn0; m1 = mn1;
        #pragma unroll
        for (int f = 0; f < 16; f++) {
            o[f][0] *= al0; o[f][1] *= al0; o[f][2] *= al1; o[f][3] *= al1;
        }

        // pack P into A-fragments directly (FA2 register identity)
        uint32_t pp[4][4];
        #pragma unroll
        for (int t = 0; t < 4; t++) {
            __half2 ha = __floats2half2_rn(sc[2 * t][0],     sc[2 * t][1]);
            __half2 hb = __floats2half2_rn(sc[2 * t][2],     sc[2 * t][3]);
            __half2 hc = __floats2half2_rn(sc[2 * t + 1][0], sc[2 * t + 1][1]);
            __half2 hd = __floats2half2_rn(sc[2 * t + 1][2], sc[2 * t + 1][3]);
            pp[t][0] = *(const uint32_t*)&ha;
            pp[t][1] = *(const uint32_t*)&hb;
            pp[t][2] = *(const uint32_t*)&hc;
            pp[t][3] = *(const uint32_t*)&hd;
        }

        // O += P @ V
        #pragma unroll
        for (int kk = 0; kk < 4; kk++) {
            int kr = kk * 16 + v_kr;
            #pragma unroll
            for (int t = 0; t < 8; t++) {
                int dcol = t * 16 + v_dg;
                int chunk = dcol >> 6, g = (dcol & 63) >> 3;
                uint32_t bd = sVb + (uint32_t)(chunk * 8192 + kr * 128 + ((g ^ (kr & 7)) << 4));
                uint32_t v0, v1, v2, v3;
                ldsm4t(bd, v0, v1, v2, v3);
                mma_f16(o[2 * t],     pp[kk][0], pp[kk][1], pp[kk][2], pp[kk][3], v0, v1);
                mma_f16(o[2 * t + 1], pp[kk][0], pp[kk][1], pp[kk][2], pp[kk][3], v2, v3);
            }
        }
        scomp = (scomp == 2) ? 0 : scomp + 1;
        sfill = (sfill == 2) ? 0 : sfill + 1;
    }

    float inv0 = 1.f / l0, inv1 = 1.f / l1;
    #pragma unroll
    for (int f = 0; f < 16; f++) {
        int col = f * 8 + (lane & 3) * 2;
        *(__half2*)(O + (size_t)rg0 * (NH * HD) + h * HD + col) =
            __floats2half2_rn(o[f][0] * inv0, o[f][1] * inv0);
        *(__half2*)(O + (size_t)rg1 * (NH * HD) + h * HD + col) =
            __floats2half2_rn(o[f][2] * inv1, o[f][3] * inv1);
    }
}

// ---------------- launcher (fine-grained per-weight join events) ----------------
extern "C" void kernel_launch(void* const* d_in, const int* in_sizes, int n_in,
                              void* d_out, int out_size)
{
    const float* hs  = (const float*)d_in[0];
    const int*   cu  = (const int*)  d_in[1];
    const float* ln1 = (const float*)d_in[2];
    const float* ln2 = (const float*)d_in[3];
    const float* qw  = (const float*)d_in[4];
    const float* kw  = (const float*)d_in[5];
    const float* vw  = (const float*)d_in[6];
    const float* ow  = (const float*)d_in[7];
    const float* gw  = (const float*)d_in[8];
    const float* uw  = (const float*)d_in[9];
    const float* dw  = (const float*)d_in[10];

    float* out_hidden = (float*)d_out;
    float* out_key    = out_hidden + (size_t)LQ * HID;
    float* out_val    = out_key    + (size_t)LQ * KVW;

    __half *p_normed, *p_qh, *p_kh, *p_vh, *p_attn, *p_n2, *p_act;
    float *p_h1;
    __half *rw_q, *rw_k, *rw_v, *rw_o, *rw_g, *rw_u, *rw_d;
    cudaGetSymbolAddress((void**)&p_normed, g_normed);
    cudaGetSymbolAddress((void**)&p_qh,     g_qh);
    cudaGetSymbolAddress((void**)&p_kh,     g_kh);
    cudaGetSymbolAddress((void**)&p_vh,     g_vh);
    cudaGetSymbolAddress((void**)&p_attn,   g_attn);
    cudaGetSymbolAddress((void**)&p_h1,     g_h1);
    cudaGetSymbolAddress((void**)&p_n2,     g_n2);
    cudaGetSymbolAddress((void**)&p_act,    g_act);
    cudaGetSymbolAddress((void**)&rw_q, w_q);
    cudaGetSymbolAddress((void**)&rw_k, w_k);
    cudaGetSymbolAddress((void**)&rw_v, w_v);
    cudaGetSymbolAddress((void**)&rw_o, w_o);
    cudaGetSymbolAddress((void**)&rw_g, w_g);
    cudaGetSymbolAddress((void**)&rw_u, w_u);
    cudaGetSymbolAddress((void**)&rw_d, w_d);

    cudaFuncSetAttribute(attn_h, cudaFuncAttributeMaxDynamicSharedMemorySize, ATT_SMEM);
    int gemm_smem = 3 * 32768;  // 96KB
    cudaFuncSetAttribute(gemm_h,        cudaFuncAttributeMaxDynamicSharedMemorySize, gemm_smem);
    cudaFuncSetAttribute(gemm_qkv_h,    cudaFuncAttributeMaxDynamicSharedMemorySize, gemm_smem);
    cudaFuncSetAttribute(gemm_gateup_h, cudaFuncAttributeMaxDynamicSharedMemorySize, gemm_smem);

    // side stream + events (host objects; created per call, left for harness teardown)
    cudaStream_t s2;
    cudaStreamCreateWithFlags(&s2, cudaStreamNonBlocking);
    cudaEvent_t evFork, evO, evGU, evD;
    cudaEventCreateWithFlags(&evFork, cudaEventDisableTiming);
    cudaEventCreateWithFlags(&evO,    cudaEventDisableTiming);
    cudaEventCreateWithFlags(&evGU,   cudaEventDisableTiming);
    cudaEventCreateWithFlags(&evD,    cudaEventDisableTiming);

    // 0a) convert q/k/v weights (needed immediately) on main stream
    convert_qkv<<<dim3(512, 3), 256>>>(qw, kw, vw, rw_q, rw_k, rw_v);

    // 1) ln1 (fp16 output)
    rmsnorm_h<<<LQ, 512>>>(hs, ln1, p_normed);
    // 2) fused QKV: Q fp16 ; K,V fp32 into d_out AND fp16 copies
    gemm_qkv_h<<<dim3(24, LQ / 128), 256, gemm_smem>>>(p_normed, rw_q, rw_k, rw_v,
                                                       p_qh, out_key, out_val, p_kh, p_vh);
    // fork AFTER QKV: conversions overlap attention; per-weight events for
    // just-in-time joins (o first — O-proj's dependency clears in ~5us)
    cudaEventRecord(evFork, 0);
    cudaStreamWaitEvent(s2, evFork, 0);
    convert_o<<<512, 256, 0, s2>>>(ow, rw_o);
    cudaEventRecord(evO, s2);
    convert_gu<<<dim3(1024, 2), 256, 0, s2>>>(gw, uw, rw_g, rw_u);
    cudaEventRecord(evGU, s2);
    convert_d<<<1024, 256, 0, s2>>>(dw, rw_d);
    cudaEventRecord(evD, s2);

    // 3) fp16 flash attention (register-P, 3-stage KV, longest-first)
    attn_h<<<dim3(NH, LQ / 64), 128, ATT_SMEM>>>(p_qh, p_kh, p_vh, cu, p_attn);

    // 4) O-proj + residual (needs only w_o)
    cudaStreamWaitEvent(0, evO, 0);
    gemm_h<<<dim3(HID / 128, LQ / 128), 256, gemm_smem>>>(p_attn, rw_o, p_h1, HID, HID, hs, 1);
    // 5) ln2 (fp16 output)
    rmsnorm_h<<<LQ, 512>>>(p_h1, ln2, p_n2);
    // 6) fused gate+up+silu (needs w_g, w_u)
    cudaStreamWaitEvent(0, evGU, 0);
    gemm_gateup_h<<<dim3(INTER / 64, LQ / 128), 256, gemm_smem>>>(p_n2, rw_g, rw_u, p_act);
    // 7) down + residual -> output hidden (needs w_d)
    cudaStreamWaitEvent(0, evD, 0);
    gemm_h<<<dim3(HID / 128, LQ / 128), 256, gemm_smem>>>(p_act, rw_d, out_hidden, INTER, HID, p_h1, 1);
}